// round 14
// baseline (speedup 1.0000x reference)
#include <cuda_runtime.h>
#include <math.h>

#define N_NODE 112
#define D_L1   256
#define D_L2   128
#define D_L3   64
#define N_BATCH 2048
#define KP1    56
#define KP2    28

// Batch-independent precomputed tensors
__device__ float g_H0[N_NODE * D_L1];    // H0[n][o] = Wp1[o][n] + bp1[o]
__device__ float g_E1[N_NODE * N_NODE];  // exp(relu(s0_i + t0_j + ba1))
__device__ float g_Wp2t[D_L1 * D_L2];    // Wp2 transposed: [d][c]

__device__ __forceinline__ float wsum(float v) {
#pragma unroll
    for (int s = 16; s; s >>= 1) v += __shfl_xor_sync(0xffffffffu, v, s);
    return v;
}

// ---------------------------------------------------------------- precompute
__global__ void pre(const float* __restrict__ Wp1, const float* __restrict__ bp1,
                    const float* __restrict__ Wp2,
                    const float* __restrict__ wa1, const float* __restrict__ wb1,
                    const float* __restrict__ ba1) {
    int idx = blockIdx.x * blockDim.x + threadIdx.x;
    if (idx < N_NODE * D_L1) {
        int n = idx / D_L1, o = idx % D_L1;
        g_H0[idx] = Wp1[o * N_NODE + n] + bp1[o];
    }
    if (idx < D_L1 * D_L2) {
        int d = idx / D_L2, c = idx % D_L2;
        g_Wp2t[idx] = Wp2[c * D_L1 + d];
    }
    if (blockIdx.x == 0) {
        __shared__ float s0[N_NODE], t0[N_NODE];
        int tid = threadIdx.x, lane = tid & 31, wid = tid >> 5;  // 8 warps
        for (int i = wid; i < N_NODE; i += 8) {
            float as = 0.f, at = 0.f;
            for (int o = lane; o < D_L1; o += 32) {
                float h = Wp1[o * N_NODE + i] + bp1[o];   // == g_H0[i*D_L1+o]
                as += h * wa1[o];
                at += h * wb1[o];
            }
            as = wsum(as); at = wsum(at);
            if (!lane) { s0[i] = as; t0[i] = at; }
        }
        __syncthreads();
        float ba = ba1[0];
        for (int k = tid; k < N_NODE * N_NODE; k += blockDim.x) {
            int i = k / N_NODE, j = k % N_NODE;
            g_E1[k] = expf(fmaxf(s0[i] + t0[j] + ba, 0.f));
        }
    }
}

// ---------------------------------------------------------------- main megakernel
// smem plan (floats) — identical to R1:
//   sW   [112][116]  @0       (later reused: sa [56][57] @0, sh2 [56][128] @3192)
//   sh1  [112][256]  @12992   (later reused: sho [56][128])
//   small arrays     @41664   (~2.5 KB)
#define SW_OFF   0
#define SW_STR   116
#define SH1_OFF  12992
#define SMALL_OFF 41664
#define SA_STR   57
#define SMEM_FLOATS 42304
#define SMEM_BYTES (SMEM_FLOATS * 4)

__global__ void __launch_bounds__(1024, 1) gnn_main(
    const float* __restrict__ x,
    const float* __restrict__ Wpool1, const float* __restrict__ bpool1,
    const float* __restrict__ bp2,
    const float* __restrict__ wa2, const float* __restrict__ wb2,
    const float* __restrict__ ba2,
    const float* __restrict__ Wpool2, const float* __restrict__ bpool2,
    const float* __restrict__ Wfc1, const float* __restrict__ bfc1,
    const float* __restrict__ Wfc2, const float* __restrict__ bfc2,
    float* __restrict__ out)
{
    extern __shared__ float smem[];
    float* sW    = smem + SW_OFF;
    float* sh1   = smem + SH1_OFF;
    float* ssig1 = smem + SMALL_OFF;          // 112
    int*   idx1  = (int*)(ssig1 + 112);       // 56
    float* val1  = (float*)(idx1 + 56);       // 56
    float* s2    = val1 + 56;                 // 56
    float* t2    = s2 + 56;                   // 56
    float* ssig2 = t2 + 56;                   // 56
    int*   idx2  = (int*)(ssig2 + 56);        // 28
    float* val2  = (float*)(idx2 + 28);       // 28
    float* smean = val2 + 28;                 // 128
    float* sfc   = smean + 128;               // 64
    float* sa    = sW;                        // [56][57]
    float* sh2   = sW + 3192;                 // [56][128]
    float* sho   = sh1;                       // [56][128]

    const int tid = threadIdx.x, lane = tid & 31, wid = tid >> 5;  // 32 warps
    const int b = blockIdx.x;
    const float* xb = x + (size_t)b * N_NODE * N_NODE;

    // ---- P0: W = rownorm(E1 .* x[b]) into sW (stride 116) ----
    for (int i = wid; i < N_NODE; i += 32) {
        float part = 0.f;
#pragma unroll
        for (int jj = 0; jj < 4; jj++) {
            int j = lane + jj * 32;
            if (j < N_NODE) {
                float u = g_E1[i * N_NODE + j] * xb[i * N_NODE + j];
                sW[i * SW_STR + j] = u;
                part += u;
            }
        }
        part = wsum(part);
        float inv = 1.f / part;
#pragma unroll
        for (int jj = 0; jj < 4; jj++) {
            int j = lane + jj * 32;
            if (j < N_NODE) sW[i * SW_STR + j] *= inv;
        }
    }
    __syncthreads();

    // ---- P1: h1 = relu(W @ H0 + H0)  [112][256] ----
    // 2 output columns x 14 rows per thread (R11 form; FFMA-bound, leave as is).
    {
        const int o0 = (tid & 127) * 2;       // column pair
        const int oh = tid >> 7;              // 0..7 row group
        const int i0 = oh * 14;
        const float* h0p = g_H0 + o0;
        float accA[14], accB[14];
#pragma unroll
        for (int r = 0; r < 14; r++) {
            float2 h2i = *(const float2*)(h0p + (i0 + r) * D_L1);
            accA[r] = h2i.x; accB[r] = h2i.y;
        }
#pragma unroll 2
        for (int k = 0; k < N_NODE; k += 4) {
            const float2 h0 = *(const float2*)(h0p + (k + 0) * D_L1);
            const float2 h1 = *(const float2*)(h0p + (k + 1) * D_L1);
            const float2 h2v = *(const float2*)(h0p + (k + 2) * D_L1);
            const float2 h3 = *(const float2*)(h0p + (k + 3) * D_L1);
#pragma unroll
            for (int r = 0; r < 14; r++) {
                const float4 w4 = *(const float4*)(sW + (i0 + r) * SW_STR + k);
                accA[r] += w4.x * h0.x;  accB[r] += w4.x * h0.y;
                accA[r] += w4.y * h1.x;  accB[r] += w4.y * h1.y;
                accA[r] += w4.z * h2v.x; accB[r] += w4.z * h2v.y;
                accA[r] += w4.w * h3.x;  accB[r] += w4.w * h3.y;
            }
        }
#pragma unroll
        for (int r = 0; r < 14; r++) {
            *(float2*)(sh1 + (i0 + r) * D_L1 + o0) =
                make_float2(fmaxf(accA[r], 0.f), fmaxf(accB[r], 0.f));
        }
    }
    __syncthreads();

    // ---- P2: pool1 scores ----
    {
        float bp = bpool1[0];
        for (int i = wid; i < N_NODE; i += 32) {
            float a = 0.f;
#pragma unroll
            for (int oo = 0; oo < 8; oo++) {
                int o = lane + oo * 32;
                a += sh1[i * D_L1 + o] * Wpool1[o];
            }
            a = wsum(a);
            if (!lane) ssig1[i] = 1.f / (1.f + expf(-(a + bp)));
        }
    }
    __syncthreads();

    // ---- P3: top-56 via stable descending rank ----
    if (tid < N_NODE) {
        float sv = ssig1[tid];
        int rank = 0;
        for (int j = 0; j < N_NODE; j++) {
            float so = ssig1[j];
            rank += (so > sv) || (so == sv && j < tid);
        }
        if (rank < KP1) { idx1[rank] = tid; val1[rank] = sv; }
    }
    __syncthreads();

    // ---- P4: gather adjacency a1 = rownorm(x[gi][gj])  [56][57-padded] ----
    for (int i = wid; i < KP1; i += 32) {
        int gi = idx1[i];
        const float* xr = xb + gi * N_NODE;
        int j0 = lane, j1 = lane + 32;
        float v0 = xr[idx1[j0]];
        float v1 = (j1 < KP1) ? xr[idx1[j1]] : 0.f;
        float part = wsum(v0 + v1);
        float inv = 1.f / part;
        sa[i * SA_STR + j0] = v0 * inv;
        if (j1 < KP1) sa[i * SA_STR + j1] = v1 * inv;
    }
    // (no sync needed: P5 writes sh2 only; sync after P5 orders both)

    // ---- P5: h2 = (h1[gather]*val) @ Wp2^T + bp2  [56][128] ----
    // 512 active threads: 4 row groups x 14 rows -> Wp2t streamed 4x (was 8x).
    // Per-element d-chain verbatim R1 (d = 0..255 ascending, scalar FFMA).
    if (tid < 512) {
        const int c = tid & 127;
        const int q = tid >> 7;               // 0..3
        const int i0 = q * 14;
        int gr[14];
#pragma unroll
        for (int r = 0; r < 14; r++) gr[r] = idx1[i0 + r] * D_L1;
        float acc[14];
#pragma unroll
        for (int r = 0; r < 14; r++) acc[r] = 0.f;
#pragma unroll 2
        for (int d = 0; d < D_L1; d += 4) {
            float w0 = g_Wp2t[(d + 0) * D_L2 + c];
            float w1 = g_Wp2t[(d + 1) * D_L2 + c];
            float w2 = g_Wp2t[(d + 2) * D_L2 + c];
            float w3 = g_Wp2t[(d + 3) * D_L2 + c];
#pragma unroll
            for (int r = 0; r < 14; r++) {
                const float4 h4 = *(const float4*)(sh1 + gr[r] + d);
                acc[r] += h4.x * w0;
                acc[r] += h4.y * w1;
                acc[r] += h4.z * w2;
                acc[r] += h4.w * w3;
            }
        }
        float bc = bp2[c];
#pragma unroll
        for (int r = 0; r < 14; r++)
            sh2[(i0 + r) * D_L2 + c] = val1[i0 + r] * acc[r] + bc;
    }
    __syncthreads();

    // ---- P6: s2/t2 attention halves ----
    for (int i = wid; i < KP1; i += 32) {
        float as = 0.f, at = 0.f;
#pragma unroll
        for (int cc = 0; cc < 4; cc++) {
            int c = lane + cc * 32;
            float h = sh2[i * D_L2 + c];
            as += h * wa2[c];
            at += h * wb2[c];
        }
        as = wsum(as); at = wsum(at);
        if (!lane) { s2[i] = as; t2[i] = at; }
    }
    __syncthreads();

    // ---- P7: att2 = rownorm(exp(relu(s2_i + t2_j + ba2)) .* a1), in place ----
    {
        float bav = ba2[0];
        for (int i = wid; i < KP1; i += 32) {
            float si = s2[i];
            int j0 = lane, j1 = lane + 32;
            float w0 = expf(fmaxf(si + t2[j0] + bav, 0.f)) * sa[i * SA_STR + j0];
            float w1 = (j1 < KP1)
                     ? expf(fmaxf(si + t2[j1] + bav, 0.f)) * sa[i * SA_STR + j1]
                     : 0.f;
            float part = wsum(w0 + w1);
            float inv = 1.f / part;
            sa[i * SA_STR + j0] = w0 * inv;
            if (j1 < KP1) sa[i * SA_STR + j1] = w1 * inv;
        }
    }
    __syncthreads();

    // ---- P8: h2out = relu(att2 @ h2 + h2) -> sho (overlays dead sh1) ----
    // 448 active threads: 4 cols x 4 rows each; sh2 rows loaded as float4,
    // each sa broadcast feeds 4 FFMAs. Per-element j-chain verbatim R1.
    if (tid < 448) {
        const int c0 = (tid & 31) * 4;        // column quad
        const int q  = tid >> 5;              // 0..13
        const int i0 = q * 4;
        float4 acc[4];
#pragma unroll
        for (int r = 0; r < 4; r++)
            acc[r] = *(const float4*)(sh2 + (i0 + r) * D_L2 + c0);
#pragma unroll 2
        for (int j = 0; j < KP1; j++) {
            const float4 v = *(const float4*)(sh2 + j * D_L2 + c0);
#pragma unroll
            for (int r = 0; r < 4; r++) {
                float a = sa[(i0 + r) * SA_STR + j];
                acc[r].x += a * v.x;
                acc[r].y += a * v.y;
                acc[r].z += a * v.z;
                acc[r].w += a * v.w;
            }
        }
#pragma unroll
        for (int r = 0; r < 4; r++) {
            *(float4*)(sho + (i0 + r) * D_L2 + c0) =
                make_float4(fmaxf(acc[r].x, 0.f), fmaxf(acc[r].y, 0.f),
                            fmaxf(acc[r].z, 0.f), fmaxf(acc[r].w, 0.f));
        }
    }
    __syncthreads();

    // ---- P9: pool2 scores + top-28 (adjacency result is discarded -> skipped) ----
    {
        float bp = bpool2[0];
        for (int i = wid; i < KP1; i += 32) {
            float a = 0.f;
#pragma unroll
            for (int cc = 0; cc < 4; cc++) {
                int c = lane + cc * 32;
                a += sho[i * D_L2 + c] * Wpool2[c];
            }
            a = wsum(a);
            if (!lane) ssig2[i] = 1.f / (1.f + expf(-(a + bp)));
        }
    }
    __syncthreads();
    if (tid < KP1) {
        float sv = ssig2[tid];
        int rank = 0;
        for (int j = 0; j < KP1; j++) {
            float so = ssig2[j];
            rank += (so > sv) || (so == sv && j < tid);
        }
        if (rank < KP2) { idx2[rank] = tid; val2[rank] = sv; }
    }
    __syncthreads();

    // ---- P10: mean over the 28 kept (scaled) rows ----
    if (tid < D_L2) {
        float m = 0.f;
#pragma unroll
        for (int r = 0; r < KP2; r++)
            m += sho[idx2[r] * D_L2 + tid] * val2[r];
        smean[tid] = m * (1.f / (float)KP2);
    }
    __syncthreads();

    // ---- P11: fc1 relu ----
    if (tid < D_L3) {
        float a = bfc1[tid];
        for (int c = 0; c < D_L2; c++)
            a += smean[c] * Wfc1[tid * D_L2 + c];
        sfc[tid] = fmaxf(a, 0.f);
    }
    __syncthreads();

    // ---- P12: fc2 -> scalar ----
    if (wid == 0) {
        float a = sfc[lane] * Wfc2[lane] + sfc[lane + 32] * Wfc2[lane + 32];
        a = wsum(a);
        if (!lane) out[b] = a + bfc2[0];
    }
}

// ---------------------------------------------------------------- launch
extern "C" void kernel_launch(void* const* d_in, const int* in_sizes, int n_in,
                              void* d_out, int out_size) {
    const float* x      = (const float*)d_in[0];
    const float* Wp1    = (const float*)d_in[1];
    const float* bp1    = (const float*)d_in[2];
    const float* wa1    = (const float*)d_in[3];
    const float* wb1    = (const float*)d_in[4];
    const float* ba1    = (const float*)d_in[5];
    const float* Wpool1 = (const float*)d_in[6];
    const float* bpool1 = (const float*)d_in[7];
    const float* Wp2    = (const float*)d_in[8];
    const float* bp2    = (const float*)d_in[9];
    const float* wa2    = (const float*)d_in[10];
    const float* wb2    = (const float*)d_in[11];
    const float* ba2    = (const float*)d_in[12];
    const float* Wpool2 = (const float*)d_in[13];
    const float* bpool2 = (const float*)d_in[14];
    const float* Wfc1   = (const float*)d_in[15];
    const float* bfc1   = (const float*)d_in[16];
    const float* Wfc2   = (const float*)d_in[17];
    const float* bfc2   = (const float*)d_in[18];
    float* out = (float*)d_out;

    cudaFuncSetAttribute(gnn_main, cudaFuncAttributeMaxDynamicSharedMemorySize,
                         SMEM_BYTES);

    pre<<<128, 256>>>(Wp1, bp1, Wp2, wa1, wb1, ba1);
    gnn_main<<<N_BATCH, 1024, SMEM_BYTES>>>(
        x, Wpool1, bpool1, bp2, wa2, wb2, ba2,
        Wpool2, bpool2, Wfc1, bfc1, Wfc2, bfc2, out);
}

// round 15
// speedup vs baseline: 1.0772x; 1.0772x over previous
#include <cuda_runtime.h>
#include <math.h>

#define N_NODE 112
#define D_L1   256
#define D_L2   128
#define D_L3   64
#define N_BATCH 2048
#define KP1    56
#define KP2    28

// Batch-independent precomputed tensors
__device__ float g_H0[N_NODE * D_L1];    // H0[n][o] = Wp1[o][n] + bp1[o]
__device__ float g_E1[N_NODE * N_NODE];  // exp(relu(s0_i + t0_j + ba1))
__device__ float g_Wp2t[D_L1 * D_L2];    // Wp2 transposed: [d][c]

__device__ __forceinline__ float wsum(float v) {
#pragma unroll
    for (int s = 16; s; s >>= 1) v += __shfl_xor_sync(0xffffffffu, v, s);
    return v;
}

// ---------------------------------------------------------------- precompute
__global__ void pre(const float* __restrict__ Wp1, const float* __restrict__ bp1,
                    const float* __restrict__ Wp2,
                    const float* __restrict__ wa1, const float* __restrict__ wb1,
                    const float* __restrict__ ba1) {
    int idx = blockIdx.x * blockDim.x + threadIdx.x;
    if (idx < N_NODE * D_L1) {
        int n = idx / D_L1, o = idx % D_L1;
        g_H0[idx] = Wp1[o * N_NODE + n] + bp1[o];
    }
    if (idx < D_L1 * D_L2) {
        int d = idx / D_L2, c = idx % D_L2;
        g_Wp2t[idx] = Wp2[c * D_L1 + d];
    }
    if (blockIdx.x == 0) {
        __shared__ float s0[N_NODE], t0[N_NODE];
        int tid = threadIdx.x, lane = tid & 31, wid = tid >> 5;  // 8 warps
        for (int i = wid; i < N_NODE; i += 8) {
            float as = 0.f, at = 0.f;
            for (int o = lane; o < D_L1; o += 32) {
                float h = Wp1[o * N_NODE + i] + bp1[o];   // == g_H0[i*D_L1+o]
                as += h * wa1[o];
                at += h * wb1[o];
            }
            as = wsum(as); at = wsum(at);
            if (!lane) { s0[i] = as; t0[i] = at; }
        }
        __syncthreads();
        float ba = ba1[0];
        for (int k = tid; k < N_NODE * N_NODE; k += blockDim.x) {
            int i = k / N_NODE, j = k % N_NODE;
            g_E1[k] = expf(fmaxf(s0[i] + t0[j] + ba, 0.f));
        }
    }
}

// ---------------------------------------------------------------- main megakernel
// smem plan (floats) — identical to R1:
//   sW   [112][116]  @0       (later reused: sa [56][57] @0, sh2 [56][128] @3192,
//                              and as int scratch for parallel rank counting)
//   sh1  [112][256]  @12992   (later reused: sho [56][128])
//   small arrays     @41664   (~2.5 KB)
#define SW_OFF   0
#define SW_STR   116
#define SH1_OFF  12992
#define SMALL_OFF 41664
#define SA_STR   57
#define SMEM_FLOATS 42304
#define SMEM_BYTES (SMEM_FLOATS * 4)

__global__ void __launch_bounds__(1024, 1) gnn_main(
    const float* __restrict__ x,
    const float* __restrict__ Wpool1, const float* __restrict__ bpool1,
    const float* __restrict__ bp2,
    const float* __restrict__ wa2, const float* __restrict__ wb2,
    const float* __restrict__ ba2,
    const float* __restrict__ Wpool2, const float* __restrict__ bpool2,
    const float* __restrict__ Wfc1, const float* __restrict__ bfc1,
    const float* __restrict__ Wfc2, const float* __restrict__ bfc2,
    float* __restrict__ out)
{
    extern __shared__ float smem[];
    float* sW    = smem + SW_OFF;
    float* sh1   = smem + SH1_OFF;
    float* ssig1 = smem + SMALL_OFF;          // 112
    int*   idx1  = (int*)(ssig1 + 112);       // 56
    float* val1  = (float*)(idx1 + 56);       // 56
    float* s2    = val1 + 56;                 // 56
    float* t2    = s2 + 56;                   // 56
    float* ssig2 = t2 + 56;                   // 56
    int*   idx2  = (int*)(ssig2 + 56);        // 28
    float* val2  = (float*)(idx2 + 28);       // 28
    float* smean = val2 + 28;                 // 128
    float* sfc   = smean + 128;               // 64
    float* sa    = sW;                        // [56][57]
    float* sh2   = sW + 3192;                 // [56][128]
    float* sho   = sh1;                       // [56][128]
    int*   prank = (int*)(smem);              // scratch (sW/sa region, dead at use)

    const int tid = threadIdx.x, lane = tid & 31, wid = tid >> 5;  // 32 warps
    const int b = blockIdx.x;
    const float* xb = x + (size_t)b * N_NODE * N_NODE;

    // ---- P0: W = rownorm(E1 .* x[b]) into sW (stride 116) ----
    for (int i = wid; i < N_NODE; i += 32) {
        float part = 0.f;
#pragma unroll
        for (int jj = 0; jj < 4; jj++) {
            int j = lane + jj * 32;
            if (j < N_NODE) {
                float u = g_E1[i * N_NODE + j] * xb[i * N_NODE + j];
                sW[i * SW_STR + j] = u;
                part += u;
            }
        }
        part = wsum(part);
        float inv = 1.f / part;
#pragma unroll
        for (int jj = 0; jj < 4; jj++) {
            int j = lane + jj * 32;
            if (j < N_NODE) sW[i * SW_STR + j] *= inv;
        }
    }
    __syncthreads();

    // ---- P1: h1 = relu(W @ H0 + H0)  [112][256] ----
    // 2 output columns x 14 rows per thread (R11 form; FFMA-bound).
    {
        const int o0 = (tid & 127) * 2;       // column pair
        const int oh = tid >> 7;              // 0..7 row group
        const int i0 = oh * 14;
        const float* h0p = g_H0 + o0;
        float accA[14], accB[14];
#pragma unroll
        for (int r = 0; r < 14; r++) {
            float2 h2i = *(const float2*)(h0p + (i0 + r) * D_L1);
            accA[r] = h2i.x; accB[r] = h2i.y;
        }
#pragma unroll 2
        for (int k = 0; k < N_NODE; k += 4) {
            const float2 h0 = *(const float2*)(h0p + (k + 0) * D_L1);
            const float2 h1 = *(const float2*)(h0p + (k + 1) * D_L1);
            const float2 h2v = *(const float2*)(h0p + (k + 2) * D_L1);
            const float2 h3 = *(const float2*)(h0p + (k + 3) * D_L1);
#pragma unroll
            for (int r = 0; r < 14; r++) {
                const float4 w4 = *(const float4*)(sW + (i0 + r) * SW_STR + k);
                accA[r] += w4.x * h0.x;  accB[r] += w4.x * h0.y;
                accA[r] += w4.y * h1.x;  accB[r] += w4.y * h1.y;
                accA[r] += w4.z * h2v.x; accB[r] += w4.z * h2v.y;
                accA[r] += w4.w * h3.x;  accB[r] += w4.w * h3.y;
            }
        }
#pragma unroll
        for (int r = 0; r < 14; r++) {
            *(float2*)(sh1 + (i0 + r) * D_L1 + o0) =
                make_float2(fmaxf(accA[r], 0.f), fmaxf(accB[r], 0.f));
        }
    }
    __syncthreads();

    // ---- P2: pool1 scores ----
    {
        float bp = bpool1[0];
        for (int i = wid; i < N_NODE; i += 32) {
            float a = 0.f;
#pragma unroll
            for (int oo = 0; oo < 8; oo++) {
                int o = lane + oo * 32;
                a += sh1[i * D_L1 + o] * Wpool1[o];
            }
            a = wsum(a);
            if (!lane) ssig1[i] = 1.f / (1.f + expf(-(a + bp)));
        }
    }
    __syncthreads();

    // ---- P3: top-56 via stable descending rank, 8-way parallel ----
    // Integer partial counts are exactly associative -> rank identical to R1.
    if (tid < 896) {
        const int i  = tid >> 3;              // 0..111
        const int ch = tid & 7;               // 0..7
        const float sv = ssig1[i];
        const int j0 = ch * 14;
        int cnt = 0;
#pragma unroll
        for (int jj = 0; jj < 14; jj++) {
            int j = j0 + jj;
            float so = ssig1[j];
            cnt += (so > sv) || (so == sv && j < i);
        }
        prank[tid] = cnt;
    }
    __syncthreads();
    if (tid < N_NODE) {
        int rank = 0;
#pragma unroll
        for (int ch = 0; ch < 8; ch++) rank += prank[tid * 8 + ch];
        if (rank < KP1) { idx1[rank] = tid; val1[rank] = ssig1[tid]; }
    }
    __syncthreads();

    // ---- P4: gather adjacency a1 = rownorm(x[gi][gj])  [56][57-padded] ----
    for (int i = wid; i < KP1; i += 32) {
        int gi = idx1[i];
        const float* xr = xb + gi * N_NODE;
        int j0 = lane, j1 = lane + 32;
        float v0 = xr[idx1[j0]];
        float v1 = (j1 < KP1) ? xr[idx1[j1]] : 0.f;
        float part = wsum(v0 + v1);
        float inv = 1.f / part;
        sa[i * SA_STR + j0] = v0 * inv;
        if (j1 < KP1) sa[i * SA_STR + j1] = v1 * inv;
    }
    // (no sync needed: P5 writes sh2 only; sync after P5 orders both)

    // ---- P5: h2 = (h1[gather]*val) @ Wp2^T + bp2  [56][128] ----
    // R11 form (1024 threads, 8 groups x 7 rows); unroll 4 for deeper MLP.
    {
        const int c = tid & 127;
        const int q = tid >> 7;               // 0..7
        const int i0 = q * 7;
        int gr[7];
#pragma unroll
        for (int r = 0; r < 7; r++) gr[r] = idx1[i0 + r] * D_L1;
        float acc[7];
#pragma unroll
        for (int r = 0; r < 7; r++) acc[r] = 0.f;
#pragma unroll 4
        for (int d = 0; d < D_L1; d += 4) {
            float w0 = g_Wp2t[(d + 0) * D_L2 + c];
            float w1 = g_Wp2t[(d + 1) * D_L2 + c];
            float w2 = g_Wp2t[(d + 2) * D_L2 + c];
            float w3 = g_Wp2t[(d + 3) * D_L2 + c];
#pragma unroll
            for (int r = 0; r < 7; r++) {
                const float4 h4 = *(const float4*)(sh1 + gr[r] + d);
                acc[r] += h4.x * w0;
                acc[r] += h4.y * w1;
                acc[r] += h4.z * w2;
                acc[r] += h4.w * w3;
            }
        }
        float bc = bp2[c];
#pragma unroll
        for (int r = 0; r < 7; r++)
            sh2[(i0 + r) * D_L2 + c] = val1[i0 + r] * acc[r] + bc;
    }
    __syncthreads();

    // ---- P6: s2/t2 attention halves ----
    for (int i = wid; i < KP1; i += 32) {
        float as = 0.f, at = 0.f;
#pragma unroll
        for (int cc = 0; cc < 4; cc++) {
            int c = lane + cc * 32;
            float h = sh2[i * D_L2 + c];
            as += h * wa2[c];
            at += h * wb2[c];
        }
        as = wsum(as); at = wsum(at);
        if (!lane) { s2[i] = as; t2[i] = at; }
    }
    __syncthreads();

    // ---- P7: att2 = rownorm(exp(relu(s2_i + t2_j + ba2)) .* a1), in place ----
    {
        float bav = ba2[0];
        for (int i = wid; i < KP1; i += 32) {
            float si = s2[i];
            int j0 = lane, j1 = lane + 32;
            float w0 = expf(fmaxf(si + t2[j0] + bav, 0.f)) * sa[i * SA_STR + j0];
            float w1 = (j1 < KP1)
                     ? expf(fmaxf(si + t2[j1] + bav, 0.f)) * sa[i * SA_STR + j1]
                     : 0.f;
            float part = wsum(w0 + w1);
            float inv = 1.f / part;
            sa[i * SA_STR + j0] = w0 * inv;
            if (j1 < KP1) sa[i * SA_STR + j1] = w1 * inv;
        }
    }
    __syncthreads();

    // ---- P8: h2out = relu(att2 @ h2 + h2) -> sho (overlays dead sh1) ----
    // R11 form (896 threads, 2 cols x 4 rows); unroll 4 for deeper MLP.
    if (tid < 896) {
        const int c0 = (tid & 63) * 2;        // column pair
        const int q  = tid >> 6;              // 0..13
        const int i0 = q * 4;
        float accA[4], accB[4];
#pragma unroll
        for (int r = 0; r < 4; r++) {
            float2 t = *(const float2*)(sh2 + (i0 + r) * D_L2 + c0);
            accA[r] = t.x; accB[r] = t.y;
        }
#pragma unroll 4
        for (int j = 0; j < KP1; j++) {
            const float2 v = *(const float2*)(sh2 + j * D_L2 + c0);
#pragma unroll
            for (int r = 0; r < 4; r++) {
                float a = sa[(i0 + r) * SA_STR + j];
                accA[r] += a * v.x;
                accB[r] += a * v.y;
            }
        }
#pragma unroll
        for (int r = 0; r < 4; r++) {
            *(float2*)(sho + (i0 + r) * D_L2 + c0) =
                make_float2(fmaxf(accA[r], 0.f), fmaxf(accB[r], 0.f));
        }
    }
    __syncthreads();

    // ---- P9: pool2 scores + top-28 (8-way parallel rank; adjacency discarded) ----
    {
        float bp = bpool2[0];
        for (int i = wid; i < KP1; i += 32) {
            float a = 0.f;
#pragma unroll
            for (int cc = 0; cc < 4; cc++) {
                int c = lane + cc * 32;
                a += sho[i * D_L2 + c] * Wpool2[c];
            }
            a = wsum(a);
            if (!lane) ssig2[i] = 1.f / (1.f + expf(-(a + bp)));
        }
    }
    __syncthreads();
    if (tid < 448) {
        const int i  = tid >> 3;              // 0..55
        const int ch = tid & 7;               // 0..7
        const float sv = ssig2[i];
        const int j0 = ch * 7;
        int cnt = 0;
#pragma unroll
        for (int jj = 0; jj < 7; jj++) {
            int j = j0 + jj;
            float so = ssig2[j];
            cnt += (so > sv) || (so == sv && j < i);
        }
        prank[tid] = cnt;
    }
    __syncthreads();
    if (tid < KP1) {
        int rank = 0;
#pragma unroll
        for (int ch = 0; ch < 8; ch++) rank += prank[tid * 8 + ch];
        if (rank < KP2) { idx2[rank] = tid; val2[rank] = ssig2[tid]; }
    }
    __syncthreads();

    // ---- P10: mean over the 28 kept (scaled) rows ----
    if (tid < D_L2) {
        float m = 0.f;
#pragma unroll
        for (int r = 0; r < KP2; r++)
            m += sho[idx2[r] * D_L2 + tid] * val2[r];
        smean[tid] = m * (1.f / (float)KP2);
    }
    __syncthreads();

    // ---- P11: fc1 relu ----
    if (tid < D_L3) {
        float a = bfc1[tid];
        for (int c = 0; c < D_L2; c++)
            a += smean[c] * Wfc1[tid * D_L2 + c];
        sfc[tid] = fmaxf(a, 0.f);
    }
    __syncthreads();

    // ---- P12: fc2 -> scalar ----
    if (wid == 0) {
        float a = sfc[lane] * Wfc2[lane] + sfc[lane + 32] * Wfc2[lane + 32];
        a = wsum(a);
        if (!lane) out[b] = a + bfc2[0];
    }
}

// ---------------------------------------------------------------- launch
extern "C" void kernel_launch(void* const* d_in, const int* in_sizes, int n_in,
                              void* d_out, int out_size) {
    const float* x      = (const float*)d_in[0];
    const float* Wp1    = (const float*)d_in[1];
    const float* bp1    = (const float*)d_in[2];
    const float* wa1    = (const float*)d_in[3];
    const float* wb1    = (const float*)d_in[4];
    const float* ba1    = (const float*)d_in[5];
    const float* Wpool1 = (const float*)d_in[6];
    const float* bpool1 = (const float*)d_in[7];
    const float* Wp2    = (const float*)d_in[8];
    const float* bp2    = (const float*)d_in[9];
    const float* wa2    = (const float*)d_in[10];
    const float* wb2    = (const float*)d_in[11];
    const float* ba2    = (const float*)d_in[12];
    const float* Wpool2 = (const float*)d_in[13];
    const float* bpool2 = (const float*)d_in[14];
    const float* Wfc1   = (const float*)d_in[15];
    const float* bfc1   = (const float*)d_in[16];
    const float* Wfc2   = (const float*)d_in[17];
    const float* bfc2   = (const float*)d_in[18];
    float* out = (float*)d_out;

    cudaFuncSetAttribute(gnn_main, cudaFuncAttributeMaxDynamicSharedMemorySize,
                         SMEM_BYTES);

    pre<<<128, 256>>>(Wp1, bp1, Wp2, wa1, wb1, ba1);
    gnn_main<<<N_BATCH, 1024, SMEM_BYTES>>>(
        x, Wpool1, bpool1, bp2, wa2, wb2, ba2,
        Wpool2, bpool2, Wfc1, bfc1, Wfc2, bfc2, out);
}

// round 16
// speedup vs baseline: 1.0844x; 1.0067x over previous
#include <cuda_runtime.h>
#include <math.h>

#define N_NODE 112
#define D_L1   256
#define D_L2   128
#define D_L3   64
#define N_BATCH 2048
#define KP1    56
#define KP2    28

// Batch-independent precomputed tensors
__device__ float g_H0[N_NODE * D_L1];    // H0[n][o] = Wp1[o][n] + bp1[o]
__device__ float g_E1[N_NODE * N_NODE];  // exp(relu(s0_i + t0_j + ba1))
__device__ float g_Wp2t[D_L1 * D_L2];    // Wp2 transposed: [d][c]

__device__ __forceinline__ float wsum(float v) {
#pragma unroll
    for (int s = 16; s; s >>= 1) v += __shfl_xor_sync(0xffffffffu, v, s);
    return v;
}

// ---------------------------------------------------------------- precompute
__global__ void pre(const float* __restrict__ Wp1, const float* __restrict__ bp1,
                    const float* __restrict__ Wp2,
                    const float* __restrict__ wa1, const float* __restrict__ wb1,
                    const float* __restrict__ ba1) {
    int idx = blockIdx.x * blockDim.x + threadIdx.x;
    if (idx < N_NODE * D_L1) {
        int n = idx / D_L1, o = idx % D_L1;
        g_H0[idx] = Wp1[o * N_NODE + n] + bp1[o];
    }
    if (idx < D_L1 * D_L2) {
        int d = idx / D_L2, c = idx % D_L2;
        g_Wp2t[idx] = Wp2[c * D_L1 + d];
    }
    if (blockIdx.x == 0) {
        __shared__ float s0[N_NODE], t0[N_NODE];
        int tid = threadIdx.x, lane = tid & 31, wid = tid >> 5;  // 8 warps
        for (int i = wid; i < N_NODE; i += 8) {
            float as = 0.f, at = 0.f;
            for (int o = lane; o < D_L1; o += 32) {
                float h = Wp1[o * N_NODE + i] + bp1[o];   // == g_H0[i*D_L1+o]
                as += h * wa1[o];
                at += h * wb1[o];
            }
            as = wsum(as); at = wsum(at);
            if (!lane) { s0[i] = as; t0[i] = at; }
        }
        __syncthreads();
        float ba = ba1[0];
        for (int k = tid; k < N_NODE * N_NODE; k += blockDim.x) {
            int i = k / N_NODE, j = k % N_NODE;
            g_E1[k] = expf(fmaxf(s0[i] + t0[j] + ba, 0.f));
        }
    }
}

// ---------------------------------------------------------------- main megakernel
// smem plan (floats):
//   sW   [112][116]  @0       (later reused: sa [56][60] @0..3360,
//                              sh2 [56][128] @3392..10560)
//   sh1  [112][256]  @12992   (later reused: sho [56][128])
//   small arrays     @41664   (~2.5 KB)
#define SW_OFF   0
#define SW_STR   116
#define SH1_OFF  12992
#define SMALL_OFF 41664
#define SA_STR   60
#define SH2_OFF  3392
#define SMEM_FLOATS 42304
#define SMEM_BYTES (SMEM_FLOATS * 4)

__global__ void __launch_bounds__(1024, 1) gnn_main(
    const float* __restrict__ x,
    const float* __restrict__ Wpool1, const float* __restrict__ bpool1,
    const float* __restrict__ bp2,
    const float* __restrict__ wa2, const float* __restrict__ wb2,
    const float* __restrict__ ba2,
    const float* __restrict__ Wpool2, const float* __restrict__ bpool2,
    const float* __restrict__ Wfc1, const float* __restrict__ bfc1,
    const float* __restrict__ Wfc2, const float* __restrict__ bfc2,
    float* __restrict__ out)
{
    extern __shared__ float smem[];
    float* sW    = smem + SW_OFF;
    float* sh1   = smem + SH1_OFF;
    float* ssig1 = smem + SMALL_OFF;          // 112
    int*   idx1  = (int*)(ssig1 + 112);       // 56
    float* val1  = (float*)(idx1 + 56);       // 56
    float* s2    = val1 + 56;                 // 56
    float* t2    = s2 + 56;                   // 56
    float* ssig2 = t2 + 56;                   // 56
    int*   idx2  = (int*)(ssig2 + 56);        // 28
    float* val2  = (float*)(idx2 + 28);       // 28
    float* smean = val2 + 28;                 // 128
    float* sfc   = smean + 128;               // 64
    float* sa    = sW;                        // [56][60]
    float* sh2   = smem + SH2_OFF;            // [56][128]
    float* sho   = sh1;                       // [56][128]

    const int tid = threadIdx.x, lane = tid & 31, wid = tid >> 5;  // 32 warps
    const int b = blockIdx.x;
    const float* xb = x + (size_t)b * N_NODE * N_NODE;

    // ---- P0: W = rownorm(E1 .* x[b]) into sW (stride 116) ----
    for (int i = wid; i < N_NODE; i += 32) {
        float part = 0.f;
#pragma unroll
        for (int jj = 0; jj < 4; jj++) {
            int j = lane + jj * 32;
            if (j < N_NODE) {
                float u = g_E1[i * N_NODE + j] * xb[i * N_NODE + j];
                sW[i * SW_STR + j] = u;
                part += u;
            }
        }
        part = wsum(part);
        float inv = 1.f / part;
#pragma unroll
        for (int jj = 0; jj < 4; jj++) {
            int j = lane + jj * 32;
            if (j < N_NODE) sW[i * SW_STR + j] *= inv;
        }
    }
    __syncthreads();

    // ---- P1: h1 = relu(W @ H0 + H0)  [112][256] ----
    // 2 output columns x 14 rows per thread; per-element k-chain verbatim R1.
    {
        const int o0 = (tid & 127) * 2;       // column pair
        const int oh = tid >> 7;              // 0..7 row group
        const int i0 = oh * 14;
        const float* h0p = g_H0 + o0;
        float accA[14], accB[14];
#pragma unroll
        for (int r = 0; r < 14; r++) {
            float2 h2i = *(const float2*)(h0p + (i0 + r) * D_L1);
            accA[r] = h2i.x; accB[r] = h2i.y;
        }
#pragma unroll 2
        for (int k = 0; k < N_NODE; k += 4) {
            const float2 h0 = *(const float2*)(h0p + (k + 0) * D_L1);
            const float2 h1 = *(const float2*)(h0p + (k + 1) * D_L1);
            const float2 h2v = *(const float2*)(h0p + (k + 2) * D_L1);
            const float2 h3 = *(const float2*)(h0p + (k + 3) * D_L1);
#pragma unroll
            for (int r = 0; r < 14; r++) {
                const float4 w4 = *(const float4*)(sW + (i0 + r) * SW_STR + k);
                accA[r] += w4.x * h0.x;  accB[r] += w4.x * h0.y;
                accA[r] += w4.y * h1.x;  accB[r] += w4.y * h1.y;
                accA[r] += w4.z * h2v.x; accB[r] += w4.z * h2v.y;
                accA[r] += w4.w * h3.x;  accB[r] += w4.w * h3.y;
            }
        }
#pragma unroll
        for (int r = 0; r < 14; r++) {
            *(float2*)(sh1 + (i0 + r) * D_L1 + o0) =
                make_float2(fmaxf(accA[r], 0.f), fmaxf(accB[r], 0.f));
        }
    }
    __syncthreads();

    // ---- P2: pool1 scores ----
    {
        float bp = bpool1[0];
        for (int i = wid; i < N_NODE; i += 32) {
            float a = 0.f;
#pragma unroll
            for (int oo = 0; oo < 8; oo++) {
                int o = lane + oo * 32;
                a += sh1[i * D_L1 + o] * Wpool1[o];
            }
            a = wsum(a);
            if (!lane) ssig1[i] = 1.f / (1.f + expf(-(a + bp)));
        }
    }
    __syncthreads();

    // ---- P3: top-56 via stable descending rank (8-way + shfl combine) ----
    // Integer partial counts are exactly associative -> rank identical to R1.
    if (tid < 896) {
        const int i  = tid >> 3;              // 0..111
        const int ch = tid & 7;               // 0..7
        const float sv = ssig1[i];
        const int j0 = ch * 14;
        int cnt = 0;
#pragma unroll
        for (int jj = 0; jj < 14; jj++) {
            int j = j0 + jj;
            float so = ssig1[j];
            cnt += (so > sv) || (so == sv && j < i);
        }
        cnt += __shfl_down_sync(0xffffffffu, cnt, 4, 8);
        cnt += __shfl_down_sync(0xffffffffu, cnt, 2, 8);
        cnt += __shfl_down_sync(0xffffffffu, cnt, 1, 8);
        if (ch == 0 && cnt < KP1) { idx1[cnt] = i; val1[cnt] = sv; }
    }
    __syncthreads();

    // ---- P4: gather adjacency a1 = rownorm(x[gi][gj])  [56][60-padded] ----
    for (int i = wid; i < KP1; i += 32) {
        int gi = idx1[i];
        const float* xr = xb + gi * N_NODE;
        int j0 = lane, j1 = lane + 32;
        float v0 = xr[idx1[j0]];
        float v1 = (j1 < KP1) ? xr[idx1[j1]] : 0.f;
        float part = wsum(v0 + v1);
        float inv = 1.f / part;
        sa[i * SA_STR + j0] = v0 * inv;
        if (j1 < KP1) sa[i * SA_STR + j1] = v1 * inv;
    }
    // (no sync needed: P5 writes sh2 @3392.. only; sa @0..3360 disjoint;
    //  sync after P5 orders both)

    // ---- P5: h2 = (h1[gather]*val) @ Wp2^T + bp2  [56][128] ----
    {
        const int c = tid & 127;
        const int q = tid >> 7;               // 0..7
        const int i0 = q * 7;
        int gr[7];
#pragma unroll
        for (int r = 0; r < 7; r++) gr[r] = idx1[i0 + r] * D_L1;
        float acc[7];
#pragma unroll
        for (int r = 0; r < 7; r++) acc[r] = 0.f;
#pragma unroll 4
        for (int d = 0; d < D_L1; d += 4) {
            float w0 = g_Wp2t[(d + 0) * D_L2 + c];
            float w1 = g_Wp2t[(d + 1) * D_L2 + c];
            float w2 = g_Wp2t[(d + 2) * D_L2 + c];
            float w3 = g_Wp2t[(d + 3) * D_L2 + c];
#pragma unroll
            for (int r = 0; r < 7; r++) {
                const float4 h4 = *(const float4*)(sh1 + gr[r] + d);
                acc[r] += h4.x * w0;
                acc[r] += h4.y * w1;
                acc[r] += h4.z * w2;
                acc[r] += h4.w * w3;
            }
        }
        float bc = bp2[c];
#pragma unroll
        for (int r = 0; r < 7; r++)
            sh2[(i0 + r) * D_L2 + c] = val1[i0 + r] * acc[r] + bc;
    }
    __syncthreads();

    // ---- P6: s2/t2 attention halves ----
    for (int i = wid; i < KP1; i += 32) {
        float as = 0.f, at = 0.f;
#pragma unroll
        for (int cc = 0; cc < 4; cc++) {
            int c = lane + cc * 32;
            float h = sh2[i * D_L2 + c];
            as += h * wa2[c];
            at += h * wb2[c];
        }
        as = wsum(as); at = wsum(at);
        if (!lane) { s2[i] = as; t2[i] = at; }
    }
    __syncthreads();

    // ---- P7: att2 = rownorm(exp(relu(s2_i + t2_j + ba2)) .* a1), in place ----
    {
        float bav = ba2[0];
        for (int i = wid; i < KP1; i += 32) {
            float si = s2[i];
            int j0 = lane, j1 = lane + 32;
            float w0 = expf(fmaxf(si + t2[j0] + bav, 0.f)) * sa[i * SA_STR + j0];
            float w1 = (j1 < KP1)
                     ? expf(fmaxf(si + t2[j1] + bav, 0.f)) * sa[i * SA_STR + j1]
                     : 0.f;
            float part = wsum(w0 + w1);
            float inv = 1.f / part;
            sa[i * SA_STR + j0] = w0 * inv;
            if (j1 < KP1) sa[i * SA_STR + j1] = w1 * inv;
        }
    }
    __syncthreads();

    // ---- P8: h2out = relu(att2 @ h2 + h2) -> sho (overlays dead sh1) ----
    // 896 threads, 2 cols x 4 rows; sa loaded as float4 over j (SA_STR=60 keeps
    // 16B alignment) -> 1 broadcast wf covers 4 j's. Per-element j-chain
    // verbatim R1 (j ascending, residual init).
    if (tid < 896) {
        const int c0 = (tid & 63) * 2;        // column pair
        const int q  = tid >> 6;              // 0..13
        const int i0 = q * 4;
        float accA[4], accB[4];
#pragma unroll
        for (int r = 0; r < 4; r++) {
            float2 t = *(const float2*)(sh2 + (i0 + r) * D_L2 + c0);
            accA[r] = t.x; accB[r] = t.y;
        }
#pragma unroll 2
        for (int j4 = 0; j4 < KP1; j4 += 4) {
            float4 a4[4];
#pragma unroll
            for (int r = 0; r < 4; r++)
                a4[r] = *(const float4*)(sa + (i0 + r) * SA_STR + j4);
            const float2 v0 = *(const float2*)(sh2 + (j4 + 0) * D_L2 + c0);
#pragma unroll
            for (int r = 0; r < 4; r++) { accA[r] += a4[r].x * v0.x; accB[r] += a4[r].x * v0.y; }
            const float2 v1 = *(const float2*)(sh2 + (j4 + 1) * D_L2 + c0);
#pragma unroll
            for (int r = 0; r < 4; r++) { accA[r] += a4[r].y * v1.x; accB[r] += a4[r].y * v1.y; }
            const float2 v2 = *(const float2*)(sh2 + (j4 + 2) * D_L2 + c0);
#pragma unroll
            for (int r = 0; r < 4; r++) { accA[r] += a4[r].z * v2.x; accB[r] += a4[r].z * v2.y; }
            const float2 v3 = *(const float2*)(sh2 + (j4 + 3) * D_L2 + c0);
#pragma unroll
            for (int r = 0; r < 4; r++) { accA[r] += a4[r].w * v3.x; accB[r] += a4[r].w * v3.y; }
        }
#pragma unroll
        for (int r = 0; r < 4; r++) {
            *(float2*)(sho + (i0 + r) * D_L2 + c0) =
                make_float2(fmaxf(accA[r], 0.f), fmaxf(accB[r], 0.f));
        }
    }
    __syncthreads();

    // ---- P9: pool2 scores + top-28 (8-way rank + shfl combine) ----
    {
        float bp = bpool2[0];
        for (int i = wid; i < KP1; i += 32) {
            float a = 0.f;
#pragma unroll
            for (int cc = 0; cc < 4; cc++) {
                int c = lane + cc * 32;
                a += sho[i * D_L2 + c] * Wpool2[c];
            }
            a = wsum(a);
            if (!lane) ssig2[i] = 1.f / (1.f + expf(-(a + bp)));
        }
    }
    __syncthreads();
    if (tid < 448) {
        const int i  = tid >> 3;              // 0..55
        const int ch = tid & 7;               // 0..7
        const float sv = ssig2[i];
        const int j0 = ch * 7;
        int cnt = 0;
#pragma unroll
        for (int jj = 0; jj < 7; jj++) {
            int j = j0 + jj;
            float so = ssig2[j];
            cnt += (so > sv) || (so == sv && j < i);
        }
        cnt += __shfl_down_sync(0xffffffffu, cnt, 4, 8);
        cnt += __shfl_down_sync(0xffffffffu, cnt, 2, 8);
        cnt += __shfl_down_sync(0xffffffffu, cnt, 1, 8);
        if (ch == 0 && cnt < KP2) { idx2[cnt] = i; val2[cnt] = sv; }
    }
    __syncthreads();

    // ---- P10: mean over the 28 kept (scaled) rows ----
    if (tid < D_L2) {
        float m = 0.f;
#pragma unroll
        for (int r = 0; r < KP2; r++)
            m += sho[idx2[r] * D_L2 + tid] * val2[r];
        smean[tid] = m * (1.f / (float)KP2);
    }
    __syncthreads();

    // ---- P11: fc1 relu ----
    if (tid < D_L3) {
        float a = bfc1[tid];
        for (int c = 0; c < D_L2; c++)
            a += smean[c] * Wfc1[tid * D_L2 + c];
        sfc[tid] = fmaxf(a, 0.f);
    }
    __syncthreads();

    // ---- P12: fc2 -> scalar ----
    if (wid == 0) {
        float a = sfc[lane] * Wfc2[lane] + sfc[lane + 32] * Wfc2[lane + 32];
        a = wsum(a);
        if (!lane) out[b] = a + bfc2[0];
    }
}

// ---------------------------------------------------------------- launch
extern "C" void kernel_launch(void* const* d_in, const int* in_sizes, int n_in,
                              void* d_out, int out_size) {
    const float* x      = (const float*)d_in[0];
    const float* Wp1    = (const float*)d_in[1];
    const float* bp1    = (const float*)d_in[2];
    const float* wa1    = (const float*)d_in[3];
    const float* wb1    = (const float*)d_in[4];
    const float* ba1    = (const float*)d_in[5];
    const float* Wpool1 = (const float*)d_in[6];
    const float* bpool1 = (const float*)d_in[7];
    const float* Wp2    = (const float*)d_in[8];
    const float* bp2    = (const float*)d_in[9];
    const float* wa2    = (const float*)d_in[10];
    const float* wb2    = (const float*)d_in[11];
    const float* ba2    = (const float*)d_in[12];
    const float* Wpool2 = (const float*)d_in[13];
    const float* bpool2 = (const float*)d_in[14];
    const float* Wfc1   = (const float*)d_in[15];
    const float* bfc1   = (const float*)d_in[16];
    const float* Wfc2   = (const float*)d_in[17];
    const float* bfc2   = (const float*)d_in[18];
    float* out = (float*)d_out;

    cudaFuncSetAttribute(gnn_main, cudaFuncAttributeMaxDynamicSharedMemorySize,
                         SMEM_BYTES);

    pre<<<128, 256>>>(Wp1, bp1, Wp2, wa1, wb1, ba1);
    gnn_main<<<N_BATCH, 1024, SMEM_BYTES>>>(
        x, Wpool1, bpool1, bp2, wa2, wb2, ba2,
        Wpool2, bpool2, Wfc1, bfc1, Wfc2, bfc2, out);
}

// round 17
// speedup vs baseline: 1.1390x; 1.0503x over previous
#include <cuda_runtime.h>
#include <math.h>

#define N_NODE 112
#define D_L1   256
#define D_L2   128
#define D_L3   64
#define N_BATCH 2048
#define KP1    56
#define KP2    28
#define H1_STR (N_NODE * D_L1)   // 28672 floats per batch

// Batch-independent precomputed tensors
__device__ float g_H0[N_NODE * D_L1];    // H0[n][o] = Wp1[o][n] + bp1[o]
__device__ float g_E1[N_NODE * N_NODE];  // exp(relu(s0_i + t0_j + ba1))
__device__ float g_Wp2t[D_L1 * D_L2];    // Wp2 transposed: [d][c]
__device__ float g_h1[(size_t)N_BATCH * H1_STR];  // staged h1 (235 MB)

__device__ __forceinline__ float wsum(float v) {
#pragma unroll
    for (int s = 16; s; s >>= 1) v += __shfl_xor_sync(0xffffffffu, v, s);
    return v;
}

// ---------------------------------------------------------------- precompute
__global__ void pre(const float* __restrict__ Wp1, const float* __restrict__ bp1,
                    const float* __restrict__ Wp2,
                    const float* __restrict__ wa1, const float* __restrict__ wb1,
                    const float* __restrict__ ba1) {
    int idx = blockIdx.x * blockDim.x + threadIdx.x;
    if (idx < N_NODE * D_L1) {
        int n = idx / D_L1, o = idx % D_L1;
        g_H0[idx] = Wp1[o * N_NODE + n] + bp1[o];
    }
    if (idx < D_L1 * D_L2) {
        int d = idx / D_L2, c = idx % D_L2;
        g_Wp2t[idx] = Wp2[c * D_L1 + d];
    }
    if (blockIdx.x == 0) {
        __shared__ float s0[N_NODE], t0[N_NODE];
        int tid = threadIdx.x, lane = tid & 31, wid = tid >> 5;  // 8 warps
        for (int i = wid; i < N_NODE; i += 8) {
            float as = 0.f, at = 0.f;
            for (int o = lane; o < D_L1; o += 32) {
                float h = Wp1[o * N_NODE + i] + bp1[o];   // == g_H0[i*D_L1+o]
                as += h * wa1[o];
                at += h * wb1[o];
            }
            as = wsum(as); at = wsum(at);
            if (!lane) { s0[i] = as; t0[i] = at; }
        }
        __syncthreads();
        float ba = ba1[0];
        for (int k = tid; k < N_NODE * N_NODE; k += blockDim.x) {
            int i = k / N_NODE, j = k % N_NODE;
            g_E1[k] = expf(fmaxf(s0[i] + t0[j] + ba, 0.f));
        }
    }
}

// ================================================================ kernel A
// P0 + P1, occupancy 2. smem = sW [112][116] only (51968 B).
#define SW_STR   116
#define SMEM_A_BYTES (N_NODE * SW_STR * 4)

__global__ void __launch_bounds__(512, 2) gnnA(const float* __restrict__ x) {
    extern __shared__ float smem[];
    float* sW = smem;
    const int tid = threadIdx.x, lane = tid & 31, wid = tid >> 5;  // 16 warps
    const int b = blockIdx.x;
    const float* xb = x + (size_t)b * N_NODE * N_NODE;

    // ---- P0: W = rownorm(E1 .* x[b]) into sW (verbatim R1 chain) ----
    for (int i = wid; i < N_NODE; i += 16) {
        float part = 0.f;
#pragma unroll
        for (int jj = 0; jj < 4; jj++) {
            int j = lane + jj * 32;
            if (j < N_NODE) {
                float u = g_E1[i * N_NODE + j] * xb[i * N_NODE + j];
                sW[i * SW_STR + j] = u;
                part += u;
            }
        }
        part = wsum(part);
        float inv = 1.f / part;
#pragma unroll
        for (int jj = 0; jj < 4; jj++) {
            int j = lane + jj * 32;
            if (j < N_NODE) sW[i * SW_STR + j] *= inv;
        }
    }
    __syncthreads();

    // ---- P1: h1 = relu(W @ H0 + H0) -> g_h1 (per-element k-chain verbatim) ----
    {
        const int o0 = (tid & 127) * 2;       // column pair
        const int oh = tid >> 7;              // 0..3
        const float* h0p = g_H0 + o0;
        float* h1out = g_h1 + (size_t)b * H1_STR + o0;
        for (int ibb = 0; ibb < 2; ibb++) {
            const int i0 = (oh * 2 + ibb) * 14;
            float accA[14], accB[14];
#pragma unroll
            for (int r = 0; r < 14; r++) {
                float2 h2i = *(const float2*)(h0p + (i0 + r) * D_L1);
                accA[r] = h2i.x; accB[r] = h2i.y;
            }
#pragma unroll 2
            for (int k = 0; k < N_NODE; k += 4) {
                const float2 h0 = *(const float2*)(h0p + (k + 0) * D_L1);
                const float2 h1 = *(const float2*)(h0p + (k + 1) * D_L1);
                const float2 h2v = *(const float2*)(h0p + (k + 2) * D_L1);
                const float2 h3 = *(const float2*)(h0p + (k + 3) * D_L1);
#pragma unroll
                for (int r = 0; r < 14; r++) {
                    const float4 w4 = *(const float4*)(sW + (i0 + r) * SW_STR + k);
                    accA[r] += w4.x * h0.x;  accB[r] += w4.x * h0.y;
                    accA[r] += w4.y * h1.x;  accB[r] += w4.y * h1.y;
                    accA[r] += w4.z * h2v.x; accB[r] += w4.z * h2v.y;
                    accA[r] += w4.w * h3.x;  accB[r] += w4.w * h3.y;
                }
            }
#pragma unroll
            for (int r = 0; r < 14; r++) {
                *(float2*)(h1out + (i0 + r) * D_L1) =
                    make_float2(fmaxf(accA[r], 0.f), fmaxf(accB[r], 0.f));
            }
        }
    }
}

// ================================================================ kernel B
// P2..P12, occupancy 2. smem (floats):
//   sa   [56][60]   @0      (3360; pad to 3392)
//   sh2  [56][128]  @3392   (7168) -> ..10560
//   small arrays    @10560  (640)  -> ..11200 (pad to 11264)
//   sh1g [56][256]  @11264  (14336) -> ..25600   (sho overlays @11264 after P5)
#define SA_STR   60
#define SH2_OFF  3392
#define SMALLB_OFF 10560
#define SH1G_OFF 11264
#define SMEM_B_FLOATS 25600
#define SMEM_B_BYTES (SMEM_B_FLOATS * 4)

__global__ void __launch_bounds__(512, 2) gnnB(
    const float* __restrict__ x,
    const float* __restrict__ Wpool1, const float* __restrict__ bpool1,
    const float* __restrict__ bp2,
    const float* __restrict__ wa2, const float* __restrict__ wb2,
    const float* __restrict__ ba2,
    const float* __restrict__ Wpool2, const float* __restrict__ bpool2,
    const float* __restrict__ Wfc1, const float* __restrict__ bfc1,
    const float* __restrict__ Wfc2, const float* __restrict__ bfc2,
    float* __restrict__ out)
{
    extern __shared__ float smem[];
    float* sa    = smem;                      // [56][60]
    float* sh2   = smem + SH2_OFF;            // [56][128]
    float* ssig1 = smem + SMALLB_OFF;         // 112
    int*   idx1  = (int*)(ssig1 + 112);       // 56
    float* val1  = (float*)(idx1 + 56);       // 56
    float* s2    = val1 + 56;                 // 56
    float* t2    = s2 + 56;                   // 56
    float* ssig2 = t2 + 56;                   // 56
    int*   idx2  = (int*)(ssig2 + 56);        // 28
    float* val2  = (float*)(idx2 + 28);       // 28
    float* smean = val2 + 28;                 // 128
    float* sfc   = smean + 128;               // 64
    float* sh1g  = smem + SH1G_OFF;           // [56][256] gathered h1 rows
    float* sho   = smem + SH1G_OFF;           // [56][128] overlays sh1g post-P5

    const int tid = threadIdx.x, lane = tid & 31, wid = tid >> 5;  // 16 warps
    const int b = blockIdx.x;
    const float* xb  = x + (size_t)b * N_NODE * N_NODE;
    const float* h1b = g_h1 + (size_t)b * H1_STR;

    // ---- P2: pool1 scores (chain verbatim R1; identical h1 bits from global) ----
    {
        float bp = bpool1[0];
        for (int i = wid; i < N_NODE; i += 16) {
            float a = 0.f;
#pragma unroll
            for (int oo = 0; oo < 8; oo++) {
                int o = lane + oo * 32;
                a += h1b[i * D_L1 + o] * Wpool1[o];
            }
            a = wsum(a);
            if (!lane) ssig1[i] = 1.f / (1.f + expf(-(a + bp)));
        }
    }
    __syncthreads();

    // ---- P3: top-56 stable rank, 4-way chunks + shfl (integer-exact) ----
    if (tid < 448) {
        const int i  = tid >> 2;              // 0..111
        const int ch = tid & 3;               // 0..3
        const float sv = ssig1[i];
        const int j0 = ch * 28;
        int cnt = 0;
#pragma unroll
        for (int jj = 0; jj < 28; jj++) {
            int j = j0 + jj;
            float so = ssig1[j];
            cnt += (so > sv) || (so == sv && j < i);
        }
        cnt += __shfl_down_sync(0xffffffffu, cnt, 2, 4);
        cnt += __shfl_down_sync(0xffffffffu, cnt, 1, 4);
        if (ch == 0 && cnt < KP1) { idx1[cnt] = i; val1[cnt] = sv; }
    }
    __syncthreads();

    // ---- P4: gather adjacency a1 = rownorm(x[gi][gj])  [56][60-padded] ----
    for (int i = wid; i < KP1; i += 16) {
        int gi = idx1[i];
        const float* xr = xb + gi * N_NODE;
        int j0 = lane, j1 = lane + 32;
        float v0 = xr[idx1[j0]];
        float v1 = (j1 < KP1) ? xr[idx1[j1]] : 0.f;
        float part = wsum(v0 + v1);
        float inv = 1.f / part;
        sa[i * SA_STR + j0] = v0 * inv;
        if (j1 < KP1) sa[i * SA_STR + j1] = v1 * inv;
    }
    // ---- gather the 56 selected h1 rows into smem (value-neutral copy) ----
    for (int t = tid; t < KP1 * 64; t += 512) {
        int row = t >> 6;
        int c4  = (t & 63) * 4;
        *(float4*)(sh1g + row * D_L1 + c4) =
            *(const float4*)(h1b + idx1[row] * D_L1 + c4);
    }
    __syncthreads();

    // ---- P5: h2 = (h1[gather]*val) @ Wp2^T + bp2  [56][128] ----
    // Per-element d-chain verbatim (d ascending, scalar FFMA, same values).
    {
        const int c = tid & 127;
        const int q = tid >> 7;               // 0..3
        const int i0 = q * 14;
        float acc[14];
#pragma unroll
        for (int r = 0; r < 14; r++) acc[r] = 0.f;
#pragma unroll 4
        for (int d = 0; d < D_L1; d += 4) {
            float w0 = g_Wp2t[(d + 0) * D_L2 + c];
            float w1 = g_Wp2t[(d + 1) * D_L2 + c];
            float w2 = g_Wp2t[(d + 2) * D_L2 + c];
            float w3 = g_Wp2t[(d + 3) * D_L2 + c];
#pragma unroll
            for (int r = 0; r < 14; r++) {
                const float4 h4 = *(const float4*)(sh1g + (i0 + r) * D_L1 + d);
                acc[r] += h4.x * w0;
                acc[r] += h4.y * w1;
                acc[r] += h4.z * w2;
                acc[r] += h4.w * w3;
            }
        }
        float bc = bp2[c];
#pragma unroll
        for (int r = 0; r < 14; r++)
            sh2[(i0 + r) * D_L2 + c] = val1[i0 + r] * acc[r] + bc;
    }
    __syncthreads();

    // ---- P6: s2/t2 attention halves ----
    for (int i = wid; i < KP1; i += 16) {
        float as = 0.f, at = 0.f;
#pragma unroll
        for (int cc = 0; cc < 4; cc++) {
            int c = lane + cc * 32;
            float h = sh2[i * D_L2 + c];
            as += h * wa2[c];
            at += h * wb2[c];
        }
        as = wsum(as); at = wsum(at);
        if (!lane) { s2[i] = as; t2[i] = at; }
    }
    __syncthreads();

    // ---- P7: att2 = rownorm(exp(relu(s2_i + t2_j + ba2)) .* a1), in place ----
    {
        float bav = ba2[0];
        for (int i = wid; i < KP1; i += 16) {
            float si = s2[i];
            int j0 = lane, j1 = lane + 32;
            float w0 = expf(fmaxf(si + t2[j0] + bav, 0.f)) * sa[i * SA_STR + j0];
            float w1 = (j1 < KP1)
                     ? expf(fmaxf(si + t2[j1] + bav, 0.f)) * sa[i * SA_STR + j1]
                     : 0.f;
            float part = wsum(w0 + w1);
            float inv = 1.f / part;
            sa[i * SA_STR + j0] = w0 * inv;
            if (j1 < KP1) sa[i * SA_STR + j1] = w1 * inv;
        }
    }
    __syncthreads();

    // ---- P8: h2out = relu(att2 @ h2 + h2) -> sho (overlays dead sh1g) ----
    // 448 threads: 4 cols x 4 rows; sa float4 over j, sh2 float4 rows.
    // Per-element j-chain verbatim (j ascending, residual init).
    if (tid < 448) {
        const int c0 = (tid & 31) * 4;        // column quad
        const int q  = tid >> 5;              // 0..13
        const int i0 = q * 4;
        float4 acc[4];
#pragma unroll
        for (int r = 0; r < 4; r++)
            acc[r] = *(const float4*)(sh2 + (i0 + r) * D_L2 + c0);
#pragma unroll 2
        for (int j4 = 0; j4 < KP1; j4 += 4) {
            float4 a4[4];
#pragma unroll
            for (int r = 0; r < 4; r++)
                a4[r] = *(const float4*)(sa + (i0 + r) * SA_STR + j4);
            const float4 v0 = *(const float4*)(sh2 + (j4 + 0) * D_L2 + c0);
#pragma unroll
            for (int r = 0; r < 4; r++) {
                acc[r].x += a4[r].x * v0.x; acc[r].y += a4[r].x * v0.y;
                acc[r].z += a4[r].x * v0.z; acc[r].w += a4[r].x * v0.w;
            }
            const float4 v1 = *(const float4*)(sh2 + (j4 + 1) * D_L2 + c0);
#pragma unroll
            for (int r = 0; r < 4; r++) {
                acc[r].x += a4[r].y * v1.x; acc[r].y += a4[r].y * v1.y;
                acc[r].z += a4[r].y * v1.z; acc[r].w += a4[r].y * v1.w;
            }
            const float4 v2 = *(const float4*)(sh2 + (j4 + 2) * D_L2 + c0);
#pragma unroll
            for (int r = 0; r < 4; r++) {
                acc[r].x += a4[r].z * v2.x; acc[r].y += a4[r].z * v2.y;
                acc[r].z += a4[r].z * v2.z; acc[r].w += a4[r].z * v2.w;
            }
            const float4 v3 = *(const float4*)(sh2 + (j4 + 3) * D_L2 + c0);
#pragma unroll
            for (int r = 0; r < 4; r++) {
                acc[r].x += a4[r].w * v3.x; acc[r].y += a4[r].w * v3.y;
                acc[r].z += a4[r].w * v3.z; acc[r].w += a4[r].w * v3.w;
            }
        }
#pragma unroll
        for (int r = 0; r < 4; r++) {
            *(float4*)(sho + (i0 + r) * D_L2 + c0) =
                make_float4(fmaxf(acc[r].x, 0.f), fmaxf(acc[r].y, 0.f),
                            fmaxf(acc[r].z, 0.f), fmaxf(acc[r].w, 0.f));
        }
    }
    __syncthreads();

    // ---- P9: pool2 scores + top-28 (4-way rank + shfl; integer-exact) ----
    {
        float bp = bpool2[0];
        for (int i = wid; i < KP1; i += 16) {
            float a = 0.f;
#pragma unroll
            for (int cc = 0; cc < 4; cc++) {
                int c = lane + cc * 32;
                a += sho[i * D_L2 + c] * Wpool2[c];
            }
            a = wsum(a);
            if (!lane) ssig2[i] = 1.f / (1.f + expf(-(a + bp)));
        }
    }
    __syncthreads();
    if (tid < 224) {
        const int i  = tid >> 2;              // 0..55
        const int ch = tid & 3;               // 0..3
        const float sv = ssig2[i];
        const int j0 = ch * 14;
        int cnt = 0;
#pragma unroll
        for (int jj = 0; jj < 14; jj++) {
            int j = j0 + jj;
            float so = ssig2[j];
            cnt += (so > sv) || (so == sv && j < i);
        }
        cnt += __shfl_down_sync(0xffffffffu, cnt, 2, 4);
        cnt += __shfl_down_sync(0xffffffffu, cnt, 1, 4);
        if (ch == 0 && cnt < KP2) { idx2[cnt] = i; val2[cnt] = sv; }
    }
    __syncthreads();

    // ---- P10: mean over the 28 kept (scaled) rows ----
    if (tid < D_L2) {
        float m = 0.f;
#pragma unroll
        for (int r = 0; r < KP2; r++)
            m += sho[idx2[r] * D_L2 + tid] * val2[r];
        smean[tid] = m * (1.f / (float)KP2);
    }
    __syncthreads();

    // ---- P11: fc1 relu ----
    if (tid < D_L3) {
        float a = bfc1[tid];
        for (int c = 0; c < D_L2; c++)
            a += smean[c] * Wfc1[tid * D_L2 + c];
        sfc[tid] = fmaxf(a, 0.f);
    }
    __syncthreads();

    // ---- P12: fc2 -> scalar ----
    if (wid == 0) {
        float a = sfc[lane] * Wfc2[lane] + sfc[lane + 32] * Wfc2[lane + 32];
        a = wsum(a);
        if (!lane) out[b] = a + bfc2[0];
    }
}

// ---------------------------------------------------------------- launch
extern "C" void kernel_launch(void* const* d_in, const int* in_sizes, int n_in,
                              void* d_out, int out_size) {
    const float* x      = (const float*)d_in[0];
    const float* Wp1    = (const float*)d_in[1];
    const float* bp1    = (const float*)d_in[2];
    const float* wa1    = (const float*)d_in[3];
    const float* wb1    = (const float*)d_in[4];
    const float* ba1    = (const float*)d_in[5];
    const float* Wpool1 = (const float*)d_in[6];
    const float* bpool1 = (const float*)d_in[7];
    const float* Wp2    = (const float*)d_in[8];
    const float* bp2    = (const float*)d_in[9];
    const float* wa2    = (const float*)d_in[10];
    const float* wb2    = (const float*)d_in[11];
    const float* ba2    = (const float*)d_in[12];
    const float* Wpool2 = (const float*)d_in[13];
    const float* bpool2 = (const float*)d_in[14];
    const float* Wfc1   = (const float*)d_in[15];
    const float* bfc1   = (const float*)d_in[16];
    const float* Wfc2   = (const float*)d_in[17];
    const float* bfc2   = (const float*)d_in[18];
    float* out = (float*)d_out;

    cudaFuncSetAttribute(gnnA, cudaFuncAttributeMaxDynamicSharedMemorySize,
                         SMEM_A_BYTES);
    cudaFuncSetAttribute(gnnB, cudaFuncAttributeMaxDynamicSharedMemorySize,
                         SMEM_B_BYTES);

    pre<<<128, 256>>>(Wp1, bp1, Wp2, wa1, wb1, ba1);
    gnnA<<<N_BATCH, 512, SMEM_A_BYTES>>>(x);
    gnnB<<<N_BATCH, 512, SMEM_B_BYTES>>>(
        x, Wpool1, bpool1, bp2, wa2, wb2, ba2,
        Wpool2, bpool2, Wfc1, bfc1, Wfc2, bfc2, out);
}